// round 1
// baseline (speedup 1.0000x reference)
#include <cuda_runtime.h>
#include <math.h>

static constexpr int SEQ    = 2048;
static constexpr int HIDDEN = 2048;
static constexpr int NHEAD  = 16;
static constexpr int NKV    = 2;
static constexpr int HD     = 256;
static constexpr int QROW   = NHEAD * HD * 2;   // 8192 (query | gate per head)
static constexpr int KROW   = NKV * HD;         // 512
static constexpr int ODIM   = NHEAD * HD;       // 4096
static constexpr float ATTN_SCALE = 0.0625f;    // 256^-0.5

// Scratch (static device memory; no allocations allowed)
__device__ float g_qout[(size_t)SEQ * QROW];            // 64 MB: [t][h][0:256]=q, [256:512]=gate
__device__ float g_kbuf[(size_t)SEQ * KROW];            // 4 MB
__device__ float g_vbuf[(size_t)SEQ * KROW];            // 4 MB
__device__ float g_sbuf[(size_t)NHEAD * SEQ * SEQ];     // 256 MB scores/probs
__device__ float g_obuf[(size_t)SEQ * ODIM];            // 32 MB

// ---------------------------------------------------------------------------
// C[m,n] = alpha * sum_k A[m,k] * B[n,k]   (row-major, B transposed logically)
// Batched over blockIdx.z with per-batch offsets; optional causal tile skip.
// ---------------------------------------------------------------------------
__global__ __launch_bounds__(256) void gemm_nt(
    const float* __restrict__ A, const float* __restrict__ B, float* __restrict__ C,
    int M, int N, int K, int lda, int ldb, int ldc,
    long long batchA, int groupB, long long batchB, long long batchC,
    float alpha, int causal)
{
    A += (long long)blockIdx.z * batchA;
    B += (long long)(blockIdx.z / groupB) * batchB;
    C += (long long)blockIdx.z * batchC;
    int m0 = blockIdx.y * 64, n0 = blockIdx.x * 64;
    if (causal && n0 > m0 + 63) return;   // fully-masked tile

    __shared__ float As[16][65];
    __shared__ float Bs[16][65];
    int tid = threadIdx.x;
    int tx = tid & 15, ty = tid >> 4;
    float acc[4][4] = {};

    for (int k0 = 0; k0 < K; k0 += 16) {
        #pragma unroll
        for (int i = 0; i < 4; i++) {
            int e = tid + i * 256;
            int r = e >> 4, c = e & 15;
            As[c][r] = A[(long long)(m0 + r) * lda + k0 + c];
            Bs[c][r] = B[(long long)(n0 + r) * ldb + k0 + c];
        }
        __syncthreads();
        #pragma unroll
        for (int k = 0; k < 16; k++) {
            float a[4], b[4];
            #pragma unroll
            for (int i = 0; i < 4; i++) a[i] = As[k][ty * 4 + i];
            #pragma unroll
            for (int j = 0; j < 4; j++) b[j] = Bs[k][tx * 4 + j];
            #pragma unroll
            for (int i = 0; i < 4; i++)
                #pragma unroll
                for (int j = 0; j < 4; j++)
                    acc[i][j] = fmaf(a[i], b[j], acc[i][j]);
        }
        __syncthreads();
    }
    #pragma unroll
    for (int i = 0; i < 4; i++)
        #pragma unroll
        for (int j = 0; j < 4; j++)
            C[(long long)(m0 + ty * 4 + i) * ldc + n0 + tx * 4 + j] = acc[i][j] * alpha;
}

// ---------------------------------------------------------------------------
// C[m,n] = alpha * sum_k A[m,k] * B[k,n]   (row-major both)
// causalK truncates the K loop to k < m0+64 (valid because P upper tri is 0).
// ---------------------------------------------------------------------------
__global__ __launch_bounds__(256) void gemm_nn(
    const float* __restrict__ A, const float* __restrict__ B, float* __restrict__ C,
    int M, int N, int K, int lda, int ldb, int ldc,
    long long batchA, int groupB, long long batchB, long long batchC,
    float alpha, int causalK)
{
    A += (long long)blockIdx.z * batchA;
    B += (long long)(blockIdx.z / groupB) * batchB;
    C += (long long)blockIdx.z * batchC;
    int m0 = blockIdx.y * 64, n0 = blockIdx.x * 64;
    int kmax = causalK ? min(K, m0 + 64) : K;

    __shared__ float As[16][65];
    __shared__ float Bs[16][65];
    int tid = threadIdx.x;
    int tx = tid & 15, ty = tid >> 4;
    float acc[4][4] = {};

    for (int k0 = 0; k0 < kmax; k0 += 16) {
        #pragma unroll
        for (int i = 0; i < 4; i++) {
            int e = tid + i * 256;
            int ra = e >> 4, ca = e & 15;
            As[ca][ra] = A[(long long)(m0 + ra) * lda + k0 + ca];
            int rb = e >> 6, cb = e & 63;      // BK x BN = 16 x 64
            Bs[rb][cb] = B[(long long)(k0 + rb) * ldb + n0 + cb];
        }
        __syncthreads();
        #pragma unroll
        for (int k = 0; k < 16; k++) {
            float a[4], b[4];
            #pragma unroll
            for (int i = 0; i < 4; i++) a[i] = As[k][ty * 4 + i];
            #pragma unroll
            for (int j = 0; j < 4; j++) b[j] = Bs[k][tx * 4 + j];
            #pragma unroll
            for (int i = 0; i < 4; i++)
                #pragma unroll
                for (int j = 0; j < 4; j++)
                    acc[i][j] = fmaf(a[i], b[j], acc[i][j]);
        }
        __syncthreads();
    }
    #pragma unroll
    for (int i = 0; i < 4; i++)
        #pragma unroll
        for (int j = 0; j < 4; j++)
            C[(long long)(m0 + ty * 4 + i) * ldc + n0 + tx * 4 + j] = acc[i][j] * alpha;
}

// ---------------------------------------------------------------------------
// Fused RMSNorm (over D=256) + RoPE (first 64 dims) in place.
// One block per (token, head) row; 256 threads = one per element.
// ---------------------------------------------------------------------------
__global__ __launch_bounds__(256) void rmsnorm_rope(
    float* __restrict__ x, const float* __restrict__ w,
    const int* __restrict__ pos, int nheads, int rowStride, int headStride)
{
    int r = blockIdx.x;
    int t = r / nheads, h = r - t * nheads;
    float* row = x + (size_t)t * rowStride + (size_t)h * headStride;
    int d = threadIdx.x;
    float v = row[d];

    __shared__ float red[8];
    float s = v * v;
    #pragma unroll
    for (int o = 16; o; o >>= 1) s += __shfl_xor_sync(0xffffffffu, s, o);
    if ((d & 31) == 0) red[d >> 5] = s;
    __syncthreads();
    __shared__ float rinv;
    if (d == 0) {
        float tot = 0.f;
        #pragma unroll
        for (int i = 0; i < 8; i++) tot += red[i];
        rinv = rsqrtf(tot * (1.0f / 256.0f) + 1e-6f);
    }
    __syncthreads();
    float y = v * rinv * (1.0f + w[d]);

    __shared__ float buf[64];
    if (d < 64) buf[d] = y;
    __syncthreads();
    if (d < 32) {
        // inv_freq = theta^(-d/32), theta = 1e7; ln(1e7) = 16.118095650958322
        float inv = (float)exp(-(double)d * (16.118095650958322 / 32.0));
        float fr = (float)pos[t] * inv;
        float sn, cs;
        sincosf(fr, &sn, &cs);
        float x1 = buf[d], x2 = buf[d + 32];
        row[d]      = x1 * cs - x2 * sn;
        row[d + 32] = x2 * cs + x1 * sn;
    } else if (d >= 64) {
        row[d] = y;
    }
}

// ---------------------------------------------------------------------------
// Causal softmax over one score row (length q+1 valid); zeros the rest.
// grid = (SEQ, NHEAD), 256 threads; row kept in registers (8 per thread).
// ---------------------------------------------------------------------------
__global__ __launch_bounds__(256) void softmax_causal(float* __restrict__ S)
{
    int q = blockIdx.x, h = blockIdx.y;
    float* row = S + ((size_t)h * SEQ + q) * (size_t)SEQ;
    int n = q + 1;
    int tid = threadIdx.x;

    float vals[SEQ / 256];
    float m = -3.4e38f;
    #pragma unroll
    for (int i = 0; i < SEQ / 256; i++) {
        int k = tid + i * 256;
        float v = (k < n) ? row[k] : -3.4e38f;
        vals[i] = v;
        m = fmaxf(m, v);
    }
    __shared__ float red[8];
    #pragma unroll
    for (int o = 16; o; o >>= 1) m = fmaxf(m, __shfl_xor_sync(0xffffffffu, m, o));
    if ((tid & 31) == 0) red[tid >> 5] = m;
    __syncthreads();
    if (tid < 32) {
        float x = (tid < 8) ? red[tid] : -3.4e38f;
        #pragma unroll
        for (int o = 4; o; o >>= 1) x = fmaxf(x, __shfl_xor_sync(0xffffffffu, x, o));
        if (tid == 0) red[0] = x;
    }
    __syncthreads();
    m = red[0];
    __syncthreads();

    float ssum = 0.f;
    #pragma unroll
    for (int i = 0; i < SEQ / 256; i++) {
        int k = tid + i * 256;
        float e = (k < n) ? expf(vals[i] - m) : 0.f;
        vals[i] = e;
        ssum += e;
    }
    #pragma unroll
    for (int o = 16; o; o >>= 1) ssum += __shfl_xor_sync(0xffffffffu, ssum, o);
    if ((tid & 31) == 0) red[tid >> 5] = ssum;
    __syncthreads();
    if (tid < 32) {
        float x = (tid < 8) ? red[tid] : 0.f;
        #pragma unroll
        for (int o = 4; o; o >>= 1) x += __shfl_xor_sync(0xffffffffu, x, o);
        if (tid == 0) red[0] = x;
    }
    __syncthreads();
    float inv = 1.0f / red[0];
    #pragma unroll
    for (int i = 0; i < SEQ / 256; i++) {
        int k = tid + i * 256;
        row[k] = vals[i] * inv;   // masked lanes carry 0 -> writes exact zeros
    }
}

// o[t, h*256+d] *= sigmoid(gate[t,h,d]) where gate lives in g_qout[..., 256:512]
__global__ __launch_bounds__(256) void gate_mul(float* __restrict__ o,
                                                const float* __restrict__ qout)
{
    size_t idx = (size_t)blockIdx.x * 256 + threadIdx.x;
    int t = (int)(idx / ODIM);
    int j = (int)(idx - (size_t)t * ODIM);
    int h = j >> 8, d = j & 255;
    float g = qout[(size_t)t * QROW + (size_t)h * (2 * HD) + HD + d];
    o[idx] *= 1.0f / (1.0f + expf(-g));
}

extern "C" void kernel_launch(void* const* d_in, const int* in_sizes, int n_in,
                              void* d_out, int out_size)
{
    const int*   positions = (const int*)d_in[0];
    const float* hs  = (const float*)d_in[1];
    const float* wq  = (const float*)d_in[2];
    const float* wk  = (const float*)d_in[3];
    const float* wv  = (const float*)d_in[4];
    const float* wo  = (const float*)d_in[5];
    const float* qnw = (const float*)d_in[6];
    const float* knw = (const float*)d_in[7];
    float* out = (float*)d_out;

    float *qout, *kbuf, *vbuf, *sbuf, *obuf;
    cudaGetSymbolAddress((void**)&qout, g_qout);
    cudaGetSymbolAddress((void**)&kbuf, g_kbuf);
    cudaGetSymbolAddress((void**)&vbuf, g_vbuf);
    cudaGetSymbolAddress((void**)&sbuf, g_sbuf);
    cudaGetSymbolAddress((void**)&obuf, g_obuf);

    dim3 blk(256);

    // 1) QKV projections (C = hs @ W^T)
    gemm_nt<<<dim3(QROW / 64, SEQ / 64, 1), blk>>>(
        hs, wq, qout, SEQ, QROW, HIDDEN, HIDDEN, HIDDEN, QROW, 0, 1, 0, 0, 1.0f, 0);
    gemm_nt<<<dim3(KROW / 64, SEQ / 64, 1), blk>>>(
        hs, wk, kbuf, SEQ, KROW, HIDDEN, HIDDEN, HIDDEN, KROW, 0, 1, 0, 0, 1.0f, 0);
    gemm_nt<<<dim3(KROW / 64, SEQ / 64, 1), blk>>>(
        hs, wv, vbuf, SEQ, KROW, HIDDEN, HIDDEN, HIDDEN, KROW, 0, 1, 0, 0, 1.0f, 0);

    // 2) RMSNorm + RoPE (in place)
    rmsnorm_rope<<<SEQ * NHEAD, HD>>>(qout, qnw, positions, NHEAD, QROW, 2 * HD);
    rmsnorm_rope<<<SEQ * NKV, HD>>>(kbuf, knw, positions, NKV, KROW, HD);

    // 3) Scores: S[h,q,k] = scale * q[q,h,:] . k[k,h/8,:], causal tiles skipped
    gemm_nt<<<dim3(SEQ / 64, SEQ / 64, NHEAD), blk>>>(
        qout, kbuf, sbuf, SEQ, SEQ, HD,
        QROW, KROW, SEQ,
        /*batchA=*/2 * HD, /*groupB=*/NHEAD / NKV, /*batchB=*/HD,
        /*batchC=*/(long long)SEQ * SEQ, ATTN_SCALE, /*causal=*/1);

    // 4) Causal softmax (writes zeros above the diagonal)
    softmax_causal<<<dim3(SEQ, NHEAD), 256>>>(sbuf);

    // 5) O[q,h,:] = P[h,q,:] @ V[:,h/8,:], K-loop truncated by causality
    gemm_nn<<<dim3(HD / 64, SEQ / 64, NHEAD), blk>>>(
        sbuf, vbuf, obuf, SEQ, HD, SEQ,
        SEQ, KROW, ODIM,
        /*batchA=*/(long long)SEQ * SEQ, /*groupB=*/NHEAD / NKV, /*batchB=*/HD,
        /*batchC=*/HD, 1.0f, /*causalK=*/1);

    // 6) Gate
    gate_mul<<<(SEQ * ODIM) / 256, 256>>>(obuf, qout);

    // 7) Output projection
    gemm_nt<<<dim3(HIDDEN / 64, SEQ / 64, 1), blk>>>(
        obuf, wo, out, SEQ, HIDDEN, ODIM, ODIM, ODIM, HIDDEN, 0, 1, 0, 0, 1.0f, 0);
}

// round 3
// speedup vs baseline: 4.1599x; 4.1599x over previous
#include <cuda_runtime.h>
#include <math.h>
#include <stdint.h>

static constexpr int SEQ    = 2048;
static constexpr int HIDDEN = 2048;
static constexpr int NHEAD  = 16;
static constexpr int NKV    = 2;
static constexpr int HD     = 256;
static constexpr int QROW   = NHEAD * HD * 2;   // 8192 (query | gate per head)
static constexpr int KROW   = NKV * HD;         // 512
static constexpr int ODIM   = NHEAD * HD;       // 4096
static constexpr float ATTN_SCALE = 0.0625f;    // 256^-0.5

// Scratch (static device memory; no allocations allowed)
__device__ float g_qout[(size_t)SEQ * QROW];            // 64 MB
__device__ float g_kbuf[(size_t)SEQ * KROW];            // 4 MB  [t][kv*256+d]
__device__ float g_vtbuf[(size_t)KROW * SEQ];           // 4 MB  [kv*256+d][t]  (V transposed)
__device__ float g_sbuf[(size_t)NHEAD * SEQ * SEQ];     // 256 MB scores/probs
__device__ float g_obuf[(size_t)SEQ * ODIM];            // 32 MB

// ======================= tf32 mma.sync NT GEMM =============================
// C[m,n] = alpha * sum_k A[m,k] * B[n,k]   (both row-major, k contiguous)
// BM=128, BN=64, BK=32.  256 threads = 8 warps in 4(m) x 2(n); warp tile 32x32.
// SMEM holds tiles pre-permuted into m16n8k8 fragment order:
//   A: idx = ((s*8 + mt)*32 + lane)*4 + j + s*4      (s=k8 step, mt=16-row tile)
//   B: idx = ((s*8 + nt)*32 + lane)*2 + j + s*4      (nt=8-col tile)
// The +s*4 skew (16B) de-aliases the 4KB-periodic s-sections (STS conflicts).
static constexpr int BM = 128, BN = 64, BK = 32;
static constexpr int ASZ = 4112;   // uint32s per A buffer (4096 data + skew pad)
static constexpr int BSZ = 2064;   // uint32s per B buffer
static constexpr int SMEM_BYTES = (2 * ASZ + 2 * BSZ) * 4;  // 49408

__device__ __forceinline__ uint32_t f2tf32(float x) {
    uint32_t r;
    asm("cvt.rna.tf32.f32 %0, %1;" : "=r"(r) : "f"(x));
    return r;
}

__device__ __forceinline__ void mma_tf32(float* c, const uint32_t* a, const uint32_t* b) {
    asm volatile(
        "mma.sync.aligned.m16n8k8.row.col.f32.tf32.tf32.f32 "
        "{%0,%1,%2,%3}, {%4,%5,%6,%7}, {%8,%9}, {%0,%1,%2,%3};"
        : "+f"(c[0]), "+f"(c[1]), "+f"(c[2]), "+f"(c[3])
        : "r"(a[0]), "r"(a[1]), "r"(a[2]), "r"(a[3]), "r"(b[0]), "r"(b[1]));
}

__global__ __launch_bounds__(256, 2) void tc_gemm_nt(
    const float* __restrict__ A, const float* __restrict__ B, float* __restrict__ C,
    int K, int lda, int ldb, int ldc,
    long long batchA, int groupB, long long batchB, long long batchC,
    float alpha, int causal, int truncK)
{
    int m0 = blockIdx.y * BM, n0 = blockIdx.x * BN;
    if (causal && n0 > m0 + (BM - BN)) return;      // fully-masked score tile
    long long z = blockIdx.z;
    A += z * batchA;
    B += (z / groupB) * batchB;
    C += z * batchC;
    int kmax = truncK ? min(K, m0 + BM) : K;
    int nk = kmax >> 5;

    extern __shared__ uint32_t smem[];
    uint32_t* As = smem;              // two A buffers
    uint32_t* Bs = smem + 2 * ASZ;    // two B buffers

    int tid = threadIdx.x;
    int lane = tid & 31, wid = tid >> 5;
    int wm = wid >> 1, wn = wid & 1;

    // ---- precompute STS scatter indices + LDG coords (fixed per thread) ----
    int aIdx[4], aRow[4], aCol[4];
    #pragma unroll
    for (int i = 0; i < 4; i++) {
        int f = tid + i * 256;            // 0..1023 float4 index in 128x32 tile
        int r = f >> 3, c4 = f & 7;
        aRow[i] = r; aCol[i] = c4 * 4;
        int s = c4 >> 1, jh = c4 & 1;
        int mt = r >> 4, ri = r & 15, jl = ri >> 3;
        aIdx[i] = ((s * 8 + mt) * 32 + ((ri & 7) << 2)) * 4 + ((jh << 1) | jl) + s * 4;
    }
    int bIdx[2], bRow[2], bCol[2];
    #pragma unroll
    for (int i = 0; i < 2; i++) {
        int f = tid + i * 256;            // 0..511 float4 index in 64x32 tile
        int n = f >> 3, c4 = f & 7;
        bRow[i] = n; bCol[i] = c4 * 4;
        int s = c4 >> 1, j = c4 & 1;
        int nt = n >> 3;
        bIdx[i] = ((s * 8 + nt) * 32 + ((n & 7) << 2)) * 2 + j + s * 4;
    }

    float acc[2][4][4];
    #pragma unroll
    for (int i = 0; i < 2; i++)
        #pragma unroll
        for (int jj = 0; jj < 4; jj++)
            #pragma unroll
            for (int q = 0; q < 4; q++) acc[i][jj][q] = 0.f;

    float4 apre[4], bpre[2];

    auto ldg = [&](int k0) {
        #pragma unroll
        for (int i = 0; i < 4; i++)
            apre[i] = *reinterpret_cast<const float4*>(
                A + (long long)(m0 + aRow[i]) * lda + k0 + aCol[i]);
        #pragma unroll
        for (int i = 0; i < 2; i++)
            bpre[i] = *reinterpret_cast<const float4*>(
                B + (long long)(n0 + bRow[i]) * ldb + k0 + bCol[i]);
    };
    auto sts = [&](int buf) {
        uint32_t* a = As + buf * ASZ;
        #pragma unroll
        for (int i = 0; i < 4; i++) {
            a[aIdx[i]]      = f2tf32(apre[i].x);
            a[aIdx[i] + 4]  = f2tf32(apre[i].y);
            a[aIdx[i] + 8]  = f2tf32(apre[i].z);
            a[aIdx[i] + 12] = f2tf32(apre[i].w);
        }
        uint32_t* b = Bs + buf * BSZ;
        #pragma unroll
        for (int i = 0; i < 2; i++) {
            b[bIdx[i]]     = f2tf32(bpre[i].x);
            b[bIdx[i] + 2] = f2tf32(bpre[i].y);
            b[bIdx[i] + 4] = f2tf32(bpre[i].z);
            b[bIdx[i] + 6] = f2tf32(bpre[i].w);
        }
    };

    ldg(0);
    sts(0);
    __syncthreads();

    int buf = 0;
    for (int kt = 0; kt < nk; kt++) {
        if (kt + 1 < nk) ldg((kt + 1) << 5);

        uint32_t* a = As + buf * ASZ;
        uint32_t* b = Bs + buf * BSZ;
        #pragma unroll
        for (int s = 0; s < 4; s++) {
            uint32_t af[2][4], bf[4][2];
            #pragma unroll
            for (int mtl = 0; mtl < 2; mtl++) {
                uint4 v = *reinterpret_cast<const uint4*>(
                    a + ((s * 8 + wm * 2 + mtl) * 32 + lane) * 4 + s * 4);
                af[mtl][0] = v.x; af[mtl][1] = v.y; af[mtl][2] = v.z; af[mtl][3] = v.w;
            }
            #pragma unroll
            for (int ntl = 0; ntl < 4; ntl++) {
                uint2 v = *reinterpret_cast<const uint2*>(
                    b + ((s * 8 + wn * 4 + ntl) * 32 + lane) * 2 + s * 4);
                bf[ntl][0] = v.x; bf[ntl][1] = v.y;
            }
            #pragma unroll
            for (int mtl = 0; mtl < 2; mtl++)
                #pragma unroll
                for (int ntl = 0; ntl < 4; ntl++)
                    mma_tf32(acc[mtl][ntl], af[mtl], bf[ntl]);
        }

        if (kt + 1 < nk) {
            sts(buf ^ 1);
            __syncthreads();
            buf ^= 1;
        }
    }

    // ---- epilogue: direct STG (float2 per fragment row) ----
    int g = lane >> 2, t2 = (lane & 3) * 2;
    #pragma unroll
    for (int mtl = 0; mtl < 2; mtl++) {
        #pragma unroll
        for (int ntl = 0; ntl < 4; ntl++) {
            long long row = m0 + wm * 32 + mtl * 16 + g;
            int col = n0 + wn * 32 + ntl * 8 + t2;
            float2 v0 = make_float2(acc[mtl][ntl][0] * alpha, acc[mtl][ntl][1] * alpha);
            float2 v1 = make_float2(acc[mtl][ntl][2] * alpha, acc[mtl][ntl][3] * alpha);
            *reinterpret_cast<float2*>(C + row * ldc + col) = v0;
            *reinterpret_cast<float2*>(C + (row + 8) * ldc + col) = v1;
        }
    }
}

// ============================ elementwise kernels ==========================
__global__ __launch_bounds__(256) void rmsnorm_rope(
    float* __restrict__ x, const float* __restrict__ w,
    const int* __restrict__ pos, int nheads, int rowStride, int headStride)
{
    int r = blockIdx.x;
    int t = r / nheads, h = r - t * nheads;
    float* row = x + (size_t)t * rowStride + (size_t)h * headStride;
    int d = threadIdx.x;
    float v = row[d];

    __shared__ float red[8];
    float s = v * v;
    #pragma unroll
    for (int o = 16; o; o >>= 1) s += __shfl_xor_sync(0xffffffffu, s, o);
    if ((d & 31) == 0) red[d >> 5] = s;
    __syncthreads();
    __shared__ float rinv;
    if (d == 0) {
        float tot = 0.f;
        #pragma unroll
        for (int i = 0; i < 8; i++) tot += red[i];
        rinv = rsqrtf(tot * (1.0f / 256.0f) + 1e-6f);
    }
    __syncthreads();
    float y = v * rinv * (1.0f + w[d]);

    __shared__ float buf[64];
    if (d < 64) buf[d] = y;
    __syncthreads();
    if (d < 32) {
        float inv = (float)exp(-(double)d * (16.118095650958322 / 32.0));
        float fr = (float)pos[t] * inv;
        float sn, cs;
        sincosf(fr, &sn, &cs);
        float x1 = buf[d], x2 = buf[d + 32];
        row[d]      = x1 * cs - x2 * sn;
        row[d + 32] = x2 * cs + x1 * sn;
    } else if (d >= 64) {
        row[d] = y;
    }
}

__global__ __launch_bounds__(256) void softmax_causal(float* __restrict__ S)
{
    int q = blockIdx.x, h = blockIdx.y;
    float* row = S + ((size_t)h * SEQ + q) * (size_t)SEQ;
    int n = q + 1;
    int tid = threadIdx.x;

    float vals[SEQ / 256];
    float m = -3.4e38f;
    #pragma unroll
    for (int i = 0; i < SEQ / 256; i++) {
        int k = tid + i * 256;
        float v = (k < n) ? row[k] : -3.4e38f;
        vals[i] = v;
        m = fmaxf(m, v);
    }
    __shared__ float red[8];
    #pragma unroll
    for (int o = 16; o; o >>= 1) m = fmaxf(m, __shfl_xor_sync(0xffffffffu, m, o));
    if ((tid & 31) == 0) red[tid >> 5] = m;
    __syncthreads();
    if (tid < 32) {
        float x = (tid < 8) ? red[tid] : -3.4e38f;
        #pragma unroll
        for (int o = 4; o; o >>= 1) x = fmaxf(x, __shfl_xor_sync(0xffffffffu, x, o));
        if (tid == 0) red[0] = x;
    }
    __syncthreads();
    m = red[0];
    __syncthreads();

    float ssum = 0.f;
    #pragma unroll
    for (int i = 0; i < SEQ / 256; i++) {
        int k = tid + i * 256;
        float e = (k < n) ? expf(vals[i] - m) : 0.f;
        vals[i] = e;
        ssum += e;
    }
    #pragma unroll
    for (int o = 16; o; o >>= 1) ssum += __shfl_xor_sync(0xffffffffu, ssum, o);
    if ((tid & 31) == 0) red[tid >> 5] = ssum;
    __syncthreads();
    if (tid < 32) {
        float x = (tid < 8) ? red[tid] : 0.f;
        #pragma unroll
        for (int o = 4; o; o >>= 1) x += __shfl_xor_sync(0xffffffffu, x, o);
        if (tid == 0) red[0] = x;
    }
    __syncthreads();
    float inv = 1.0f / red[0];
    #pragma unroll
    for (int i = 0; i < SEQ / 256; i++) {
        int k = tid + i * 256;
        row[k] = vals[i] * inv;
    }
}

__global__ __launch_bounds__(256) void gate_mul(float* __restrict__ o,
                                                const float* __restrict__ qout)
{
    size_t idx = (size_t)blockIdx.x * 256 + threadIdx.x;
    int t = (int)(idx / ODIM);
    int j = (int)(idx - (size_t)t * ODIM);
    int h = j >> 8, d = j & 255;
    float g = qout[(size_t)t * QROW + (size_t)h * (2 * HD) + HD + d];
    o[idx] *= 1.0f / (1.0f + expf(-g));
}

// ============================ host launch ==================================
extern "C" void kernel_launch(void* const* d_in, const int* in_sizes, int n_in,
                              void* d_out, int out_size)
{
    const int*   positions = (const int*)d_in[0];
    const float* hs  = (const float*)d_in[1];
    const float* wq  = (const float*)d_in[2];
    const float* wk  = (const float*)d_in[3];
    const float* wv  = (const float*)d_in[4];
    const float* wo  = (const float*)d_in[5];
    const float* qnw = (const float*)d_in[6];
    const float* knw = (const float*)d_in[7];
    float* out = (float*)d_out;

    float *qout, *kbuf, *vt, *sbuf, *obuf;
    cudaGetSymbolAddress((void**)&qout, g_qout);
    cudaGetSymbolAddress((void**)&kbuf, g_kbuf);
    cudaGetSymbolAddress((void**)&vt,   g_vtbuf);
    cudaGetSymbolAddress((void**)&sbuf, g_sbuf);
    cudaGetSymbolAddress((void**)&obuf, g_obuf);

    cudaFuncSetAttribute(tc_gemm_nt, cudaFuncAttributeMaxDynamicSharedMemorySize,
                         SMEM_BYTES);

    dim3 blk(256);

    // 1) Q projection: qout = hs @ wq^T           [2048 x 8192]
    tc_gemm_nt<<<dim3(QROW / BN, SEQ / BM, 1), blk, SMEM_BYTES>>>(
        hs, wq, qout, HIDDEN, HIDDEN, HIDDEN, QROW, 0, 1, 0, 0, 1.0f, 0, 0);
    // 2) K projection: kbuf = hs @ wk^T           [2048 x 512]
    tc_gemm_nt<<<dim3(KROW / BN, SEQ / BM, 1), blk, SMEM_BYTES>>>(
        hs, wk, kbuf, HIDDEN, HIDDEN, HIDDEN, KROW, 0, 1, 0, 0, 1.0f, 0, 0);
    // 3) V^T: vt = wv @ hs^T                      [512 x 2048]
    tc_gemm_nt<<<dim3(SEQ / BN, KROW / BM, 1), blk, SMEM_BYTES>>>(
        wv, hs, vt, HIDDEN, HIDDEN, HIDDEN, SEQ, 0, 1, 0, 0, 1.0f, 0, 0);

    // 4) RMSNorm + RoPE (in place)
    rmsnorm_rope<<<SEQ * NHEAD, HD>>>(qout, qnw, positions, NHEAD, QROW, 2 * HD);
    rmsnorm_rope<<<SEQ * NKV, HD>>>(kbuf, knw, positions, NKV, KROW, HD);

    // 5) Scores: S[h][q][k] = scale * q . k  (causal tile skip)
    tc_gemm_nt<<<dim3(SEQ / BN, SEQ / BM, NHEAD), blk, SMEM_BYTES>>>(
        qout, kbuf, sbuf, HD, QROW, KROW, SEQ,
        /*batchA=*/2 * HD, /*groupB=*/NHEAD / NKV, /*batchB=*/HD,
        /*batchC=*/(long long)SEQ * SEQ, ATTN_SCALE, /*causal=*/1, 0);

    // 6) Causal softmax
    softmax_causal<<<dim3(SEQ, NHEAD), 256>>>(sbuf);

    // 7) O = P @ V  via NT with V^T (K truncated by causality)
    tc_gemm_nt<<<dim3(HD / BN, SEQ / BM, NHEAD), blk, SMEM_BYTES>>>(
        sbuf, vt, obuf, SEQ, SEQ, SEQ, ODIM,
        /*batchA=*/(long long)SEQ * SEQ, /*groupB=*/NHEAD / NKV,
        /*batchB=*/(long long)HD * SEQ, /*batchC=*/HD, 1.0f, 0, /*truncK=*/1);

    // 8) Gate
    gate_mul<<<(SEQ * ODIM) / 256, 256>>>(obuf, qout);

    // 9) Output projection: out = obuf @ wo^T
    tc_gemm_nt<<<dim3(HIDDEN / BN, SEQ / BM, 1), blk, SMEM_BYTES>>>(
        obuf, wo, out, ODIM, ODIM, ODIM, HIDDEN, 0, 1, 0, 0, 1.0f, 0, 0);
}